// round 2
// baseline (speedup 1.0000x reference)
#include <cuda_runtime.h>
#include <cstdint>

// OrbitalFeatureGNN: antisymmetrize(gnn, tmp_axis=-4) where tmp_axis is the
// S axis (S=2) and gnn acts independently per S slice (all coupling is over
// the ion axis N; weights are S-independent). gnn therefore commutes with
// flip along S, so the antisymmetrized output is identically zero:
//   0.5 * (gnn(x) - flip(gnn(flip(x)))) = 0.5 * (gnn(x) - gnn(x)) = 0.
// The reference (XLA batched ops, deterministic per batch slice) produces
// bitwise zeros. Fastest correct kernel: vectorized zero-fill of d_out.

__global__ void zero_fill_f4(float4* __restrict__ out, long long n4) {
    long long i = (long long)blockIdx.x * blockDim.x + threadIdx.x;
    long long stride = (long long)gridDim.x * blockDim.x;
    const float4 z = make_float4(0.f, 0.f, 0.f, 0.f);
    for (; i < n4; i += stride) out[i] = z;
}

__global__ void zero_fill_tail(float* __restrict__ out, long long start, long long n) {
    long long i = start + (long long)blockIdx.x * blockDim.x + threadIdx.x;
    if (i < n) out[i] = 0.0f;
}

extern "C" void kernel_launch(void* const* d_in, const int* in_sizes, int n_in,
                              void* d_out, int out_size) {
    (void)d_in; (void)in_sizes; (void)n_in;
    long long n = (long long)out_size;          // 1,048,576 floats expected
    long long n4 = n >> 2;                      // float4 count

    if (n4 > 0) {
        int threads = 256;
        long long want = (n4 + threads - 1) / threads;
        int blocks = (int)(want > 2048 ? 2048 : want);
        zero_fill_f4<<<blocks, threads>>>((float4*)d_out, n4);
    }
    long long tail_start = n4 << 2;
    long long tail = n - tail_start;
    if (tail > 0) {
        zero_fill_tail<<<1, 256>>>((float*)d_out, tail_start, n);
    }
}

// round 3
// speedup vs baseline: 1.0303x; 1.0303x over previous
#include <cuda_runtime.h>
#include <cstdint>

// OrbitalFeatureGNN: antisymmetrize(gnn, tmp_axis=-4) where tmp_axis is the
// S axis (S=2). gnn acts independently and identically on each S slice (all
// inter-element coupling is over the ion axis N; weights are S-independent),
// so gnn commutes with flip along S:
//   0.5 * (gnn(x) - flip(gnn(flip(x)))) = 0.5 * (gnn(x) - gnn(x)) = 0
// exactly (bitwise, since XLA's batched ops use identical per-slice summation
// order). Verified R1: rel_err == 0.0 with a plain zero-fill.
//
// R2: replace the fill kernel (4.4us, >90% launch/ramp overhead at DRAM=0%,
// L2=9.1%) with a single cudaMemsetAsync -> native graph memset node.
// Capture-legal: async, no alloc, no sync; same legacy stream as <<<>>>.

__global__ void zero_fill_f4(float4* __restrict__ out, long long n4) {
    long long i = (long long)blockIdx.x * blockDim.x + threadIdx.x;
    long long stride = (long long)gridDim.x * blockDim.x;
    const float4 z = make_float4(0.f, 0.f, 0.f, 0.f);
    for (; i < n4; i += stride) out[i] = z;
}

extern "C" void kernel_launch(void* const* d_in, const int* in_sizes, int n_in,
                              void* d_out, int out_size) {
    (void)d_in; (void)in_sizes; (void)n_in;

    size_t bytes = (size_t)out_size * sizeof(float);
    cudaError_t err = cudaMemsetAsync(d_out, 0, bytes, 0);

    if (err != cudaSuccess) {
        // Fallback: kernel fill (known-good from R1). Clear the error state
        // first so it doesn't poison the capture.
        (void)cudaGetLastError();
        long long n = (long long)out_size;
        long long n4 = n >> 2;
        if (n4 > 0) {
            int threads = 256;
            long long want = (n4 + threads - 1) / threads;
            int blocks = (int)(want > 2048 ? 2048 : want);
            zero_fill_f4<<<blocks, threads>>>((float4*)d_out, n4);
        }
        // out_size for this problem is 1048576 (divisible by 4); handle any
        // tail bytes via a second tiny memset-free path if ever needed.
        long long tail_start = n4 << 2;
        if (tail_start < n) {
            zero_fill_f4<<<1, 1>>>((float4*)d_out, 0); // no-op guard; tail impossible here
        }
    }
}

// round 5
// speedup vs baseline: 1.0570x; 1.0259x over previous
#include <cuda_runtime.h>
#include <cstdint>

// OrbitalFeatureGNN: antisymmetrize(gnn, tmp_axis=-4) where tmp_axis is the
// S axis (S=2). gnn acts independently and identically on each S slice (all
// inter-element coupling is over the ion axis N; weights are S-independent),
// so gnn commutes with flip along S:
//   0.5 * (gnn(x) - flip(gnn(flip(x)))) = 0.5 * (gnn(x) - gnn(x)) = 0
// exactly (bitwise). Verified R1/R2: rel_err == 0.0 with a zero-fill.
//
// R4 (R3 rerun after infra failure): leanest possible fill kernel to
// discriminate "memset node slow" vs "fixed replay-overhead floor".
// One 32B st.global.v8.f32 per thread (sm_100a 256-bit store), no loop,
// single wave: 512 blocks x 256 threads x 32B = 4MB for out_size == 1<<20.

__global__ __launch_bounds__(256, 1) void zero_fill_v8(float* __restrict__ out) {
    size_t idx = ((size_t)blockIdx.x * 256 + threadIdx.x) * 8;
    float* p = out + idx;
#if __CUDA_ARCH__ >= 1000
    asm volatile(
        "st.global.v8.f32 [%0], {%1, %1, %1, %1, %1, %1, %1, %1};"
        :: "l"(p), "f"(0.0f) : "memory");
#else
    float4 z = make_float4(0.f, 0.f, 0.f, 0.f);
    *reinterpret_cast<float4*>(p)     = z;
    *reinterpret_cast<float4*>(p + 4) = z;
#endif
}

// Generic single-kernel fallback for arbitrary out_size (grid-stride float4
// body + in-kernel scalar tail). Never taken for this problem's shapes.
__global__ void zero_fill_any(float* __restrict__ out, long long n) {
    long long n4 = n >> 2;
    float4* out4 = reinterpret_cast<float4*>(out);
    const float4 z = make_float4(0.f, 0.f, 0.f, 0.f);
    long long i = (long long)blockIdx.x * blockDim.x + threadIdx.x;
    long long stride = (long long)gridDim.x * blockDim.x;
    for (; i < n4; i += stride) out4[i] = z;
    // Scalar tail (n % 4 elements) handled by the first few threads of block 0.
    long long tail_start = n4 << 2;
    long long t = tail_start + (long long)blockIdx.x * blockDim.x + threadIdx.x;
    if (blockIdx.x == 0 && t < n) out[t] = 0.0f;
}

extern "C" void kernel_launch(void* const* d_in, const int* in_sizes, int n_in,
                              void* d_out, int out_size) {
    (void)d_in; (void)in_sizes; (void)n_in;

    long long n = (long long)out_size;              // 1,048,576 expected
    const long long per_block = 256LL * 8;          // floats per block

    if (n > 0 && n % per_block == 0) {
        int blocks = (int)(n / per_block);          // 512 for n = 1<<20
        zero_fill_v8<<<blocks, 256>>>((float*)d_out);
    } else if (n > 0) {
        int threads = 256;
        long long want = ((n >> 2) + threads - 1) / threads;
        int blocks = (int)(want > 2048 ? 2048 : (want < 1 ? 1 : want));
        zero_fill_any<<<blocks, threads>>>((float*)d_out, n);
    }
}

// round 6
// speedup vs baseline: 1.2515x; 1.1840x over previous
#include <cuda_runtime.h>
#include <cstdint>

// OrbitalFeatureGNN: antisymmetrize(gnn, tmp_axis=-4) where tmp_axis is the
// S axis (S=2). gnn acts independently and identically on each S slice (all
// inter-element coupling is over the ion axis N; weights are S-independent),
// so gnn commutes with flip along S:
//   0.5 * (gnn(x) - flip(gnn(flip(x)))) = 0.5 * (gnn(x) - gnn(x)) = 0
// exactly (bitwise). Verified rel_err == 0.0 in R1/R2/R4.
//
// R5: floor-probe tweak. R4 showed the fill kernel runs at issue=6.2%,
// L2=9.6% — duration (~4.1us) is a fixed short-kernel floor, not work.
// Shrink CTA count 4x (128 blocks x 1024 threads, one 32B st.global.v8.f32
// per thread, exactly 4MB) to minimize dispatch/drain tails. If unchanged,
// the problem is converged at the harness floor.

__global__ __launch_bounds__(1024, 1) void zero_fill_v8(float* __restrict__ out) {
    size_t idx = ((size_t)blockIdx.x * 1024 + threadIdx.x) * 8;
    float* p = out + idx;
#if __CUDA_ARCH__ >= 1000
    asm volatile(
        "st.global.v8.f32 [%0], {%1, %1, %1, %1, %1, %1, %1, %1};"
        :: "l"(p), "f"(0.0f) : "memory");
#else
    float4 z = make_float4(0.f, 0.f, 0.f, 0.f);
    *reinterpret_cast<float4*>(p)     = z;
    *reinterpret_cast<float4*>(p + 4) = z;
#endif
}

// Generic single-kernel fallback for arbitrary out_size (grid-stride float4
// body + in-kernel scalar tail). Never taken for this problem's shapes.
__global__ void zero_fill_any(float* __restrict__ out, long long n) {
    long long n4 = n >> 2;
    float4* out4 = reinterpret_cast<float4*>(out);
    const float4 z = make_float4(0.f, 0.f, 0.f, 0.f);
    long long i = (long long)blockIdx.x * blockDim.x + threadIdx.x;
    long long stride = (long long)gridDim.x * blockDim.x;
    for (; i < n4; i += stride) out4[i] = z;
    long long tail_start = n4 << 2;
    long long t = tail_start + (long long)blockIdx.x * blockDim.x + threadIdx.x;
    if (blockIdx.x == 0 && t < n) out[t] = 0.0f;
}

extern "C" void kernel_launch(void* const* d_in, const int* in_sizes, int n_in,
                              void* d_out, int out_size) {
    (void)d_in; (void)in_sizes; (void)n_in;

    long long n = (long long)out_size;              // 1,048,576 expected
    const long long per_block = 1024LL * 8;         // floats per block

    if (n > 0 && n % per_block == 0) {
        int blocks = (int)(n / per_block);          // 128 for n = 1<<20
        zero_fill_v8<<<blocks, 1024>>>((float*)d_out);
    } else if (n > 0) {
        int threads = 256;
        long long want = ((n >> 2) + threads - 1) / threads;
        int blocks = (int)(want > 2048 ? 2048 : (want < 1 ? 1 : want));
        zero_fill_any<<<blocks, threads>>>((float*)d_out, n);
    }
}